// round 3
// baseline (speedup 1.0000x reference)
#include <cuda_runtime.h>
#include <cstdint>

#define NN 50000
#define EE 800000
#define DIM 128

// Scratch (static device globals — no allocation at launch time).
__device__ float g_buf[3u * NN * DIM];        // per-type scatter accumulators, 76.8 MB
__device__ float cnt_buf[3u * NN];            // per-type in-degree counts (float, exact)
__device__ float wcat_buf[4 * DIM * DIM];     // concatenated weights, [k][o] layout, k=0..511

// ---------------------------------------------------------------------------
// Phase 0: zero accumulators
// ---------------------------------------------------------------------------
__global__ void zero_kernel() {
    const float4 z = make_float4(0.f, 0.f, 0.f, 0.f);
    size_t i = (size_t)blockIdx.x * blockDim.x + threadIdx.x;
    const size_t ng = (size_t)3 * NN * DIM / 4;   // 4.8M float4
    if (i < ng) reinterpret_cast<float4*>(g_buf)[i] = z;
    if (i < (size_t)(3 * NN) / 4) reinterpret_cast<float4*>(cnt_buf)[i] = z;
}

// ---------------------------------------------------------------------------
// Phase 0b: build Wcat[k][o] = W_{k/128}[o][k%128]  (k-major, o contiguous)
// ---------------------------------------------------------------------------
__global__ void wprep_kernel(const float* __restrict__ W0, const float* __restrict__ W1,
                             const float* __restrict__ W2, const float* __restrict__ Wh) {
    int idx = blockIdx.x * blockDim.x + threadIdx.x;   // < 512*128
    int k = idx >> 7;          // 0..511
    int o = idx & 127;
    int t = k >> 7;            // segment 0..3
    int kk = k & 127;
    const float* W = (t == 0) ? W0 : (t == 1) ? W1 : (t == 2) ? W2 : Wh;
    wcat_buf[idx] = W[o * DIM + kk];
}

// ---------------------------------------------------------------------------
// Phase 1: edge scatter. One warp per edge.
//   G_t[dst] += x[src] - x[dst];  cnt_t[dst] += 1
// ---------------------------------------------------------------------------
__global__ __launch_bounds__(256) void scatter_kernel(
    const float4* __restrict__ x4,
    const int* __restrict__ src, const int* __restrict__ dst,
    const int* __restrict__ et) {
    int warp = (int)(((size_t)blockIdx.x * blockDim.x + threadIdx.x) >> 5);
    int lane = threadIdx.x & 31;
    if (warp >= EE) return;
    int s = __ldg(src + warp);
    int d = __ldg(dst + warp);
    int t = __ldg(et + warp);

    float4 a = x4[(size_t)s * 32 + lane];
    float4 b = x4[(size_t)d * 32 + lane];
    float4 v;
    v.x = a.x - b.x; v.y = a.y - b.y; v.z = a.z - b.z; v.w = a.w - b.w;

    float* p = g_buf + ((size_t)t * NN + d) * DIM + lane * 4;
    asm volatile("red.global.add.v4.f32 [%0], {%1, %2, %3, %4};"
                 :: "l"(p), "f"(v.x), "f"(v.y), "f"(v.z), "f"(v.w) : "memory");

    if (lane == 0) atomicAdd(cnt_buf + (size_t)t * NN + d, 1.0f);
}

// ---------------------------------------------------------------------------
// Phase 2: out[N,128] = A[N,512] @ Wcat[512,128] + bias(counts)
//   A[v, k] = G_{k/128}[v][k%128]  for k<384,  x[v][k-384] for k>=384
// Tiling: BM=64 nodes x BN=128 outs per CTA, BK=16, 256 threads, 4x8 microtile.
// ---------------------------------------------------------------------------
__global__ __launch_bounds__(256) void gemm_kernel(
    const float* __restrict__ x,
    const float* __restrict__ b0, const float* __restrict__ b1,
    const float* __restrict__ b2, const float* __restrict__ bh,
    float* __restrict__ out) {
    __shared__ float As[2][16][68];    // padded 64+4 to avoid write conflicts
    __shared__ float Bs[2][16][128];
    __shared__ float bias_s[4][128];

    const int tid = threadIdx.x;
    if (tid < 128) {
        bias_s[0][tid] = b0[tid];
        bias_s[1][tid] = b1[tid];
        bias_s[2][tid] = b2[tid];
        bias_s[3][tid] = bh[tid];
    }

    const int node0 = blockIdx.x * 64;
    const int m0 = (tid >> 4) * 4;       // 0..60
    const int n0 = (tid & 15) * 8;       // 0..120

    // A-load mapping: each thread loads one float4 of a 64x16 tile
    const int a_m = tid >> 2;            // 0..63 (node row within tile)
    const int a_q = tid & 3;             // float4 index along k
    // B-load mapping: each thread loads two float4 of a 16x128 tile
    const int b_k = tid >> 5;            // 0..7
    const int b_o = (tid & 31) * 4;      // 0..124

    float acc[4][8];
#pragma unroll
    for (int i = 0; i < 4; i++)
#pragma unroll
        for (int j = 0; j < 8; j++) acc[i][j] = 0.f;

    const int av = node0 + a_m;
    const bool a_ok = (av < NN);

    // ---- tile loaders ----
    auto loadA = [&](int kt, int buf) {
        int kg = kt * 16 + a_q * 4;
        int seg = kg >> 7;
        int kk = kg & 127;
        float4 val = make_float4(0.f, 0.f, 0.f, 0.f);
        if (a_ok) {
            const float* ap = (seg < 3)
                ? (g_buf + ((size_t)seg * NN + av) * DIM + kk)
                : (x + (size_t)av * DIM + kk);
            val = *reinterpret_cast<const float4*>(ap);
        }
        As[buf][a_q * 4 + 0][a_m] = val.x;
        As[buf][a_q * 4 + 1][a_m] = val.y;
        As[buf][a_q * 4 + 2][a_m] = val.z;
        As[buf][a_q * 4 + 3][a_m] = val.w;
    };
    auto loadB = [&](int kt, int buf) {
#pragma unroll
        for (int r = 0; r < 2; r++) {
            int k = b_k + r * 8;
            float4 w = *reinterpret_cast<const float4*>(
                wcat_buf + (size_t)(kt * 16 + k) * DIM + b_o);
            *reinterpret_cast<float4*>(&Bs[buf][k][b_o]) = w;
        }
    };

    loadA(0, 0);
    loadB(0, 0);
    __syncthreads();

#pragma unroll 4
    for (int kt = 0; kt < 32; kt++) {
        int cur = kt & 1;
        int nxt = cur ^ 1;
        if (kt + 1 < 32) {
            loadA(kt + 1, nxt);
            loadB(kt + 1, nxt);
        }
#pragma unroll
        for (int k = 0; k < 16; k++) {
            float4 ra = *reinterpret_cast<const float4*>(&As[cur][k][m0]);
            float4 rb0 = *reinterpret_cast<const float4*>(&Bs[cur][k][n0]);
            float4 rb1 = *reinterpret_cast<const float4*>(&Bs[cur][k][n0 + 4]);
            float ar[4] = {ra.x, ra.y, ra.z, ra.w};
            float br[8] = {rb0.x, rb0.y, rb0.z, rb0.w, rb1.x, rb1.y, rb1.z, rb1.w};
#pragma unroll
            for (int i = 0; i < 4; i++)
#pragma unroll
                for (int j = 0; j < 8; j++)
                    acc[i][j] = fmaf(ar[i], br[j], acc[i][j]);
        }
        __syncthreads();
    }

    // ---- epilogue: add count-weighted biases, store ----
#pragma unroll
    for (int i = 0; i < 4; i++) {
        int v = node0 + m0 + i;
        if (v < NN) {
            float c0 = cnt_buf[0 * NN + v];
            float c1 = cnt_buf[1 * NN + v];
            float c2 = cnt_buf[2 * NN + v];
            float res[8];
#pragma unroll
            for (int j = 0; j < 8; j++) {
                int o = n0 + j;
                res[j] = acc[i][j]
                       + c0 * bias_s[0][o]
                       + c1 * bias_s[1][o]
                       + c2 * bias_s[2][o]
                       + bias_s[3][o];
            }
            float* op = out + (size_t)v * DIM + n0;
            *reinterpret_cast<float4*>(op)     = make_float4(res[0], res[1], res[2], res[3]);
            *reinterpret_cast<float4*>(op + 4) = make_float4(res[4], res[5], res[6], res[7]);
        }
    }
}

// ---------------------------------------------------------------------------
// Launch
// ---------------------------------------------------------------------------
extern "C" void kernel_launch(void* const* d_in, const int* in_sizes, int n_in,
                              void* d_out, int out_size) {
    const float* n_feats = (const float*)d_in[0];
    const int*   src     = (const int*)d_in[1];
    const int*   dst     = (const int*)d_in[2];
    const int*   e_feats = (const int*)d_in[3];
    const float* W0 = (const float*)d_in[4];
    const float* b0 = (const float*)d_in[5];
    const float* W1 = (const float*)d_in[6];
    const float* b1 = (const float*)d_in[7];
    const float* W2 = (const float*)d_in[8];
    const float* b2 = (const float*)d_in[9];
    const float* Wh = (const float*)d_in[10];
    const float* bh = (const float*)d_in[11];
    float* out = (float*)d_out;

    // Phase 0: zero scratch (4.8M float4 for g_buf; cnt folded in)
    {
        int total = 3 * NN * DIM / 4;
        int grid = (total + 255) / 256;
        zero_kernel<<<grid, 256>>>();
    }
    // Phase 0b: weight concat
    wprep_kernel<<<(4 * DIM * DIM) / 256, 256>>>(W0, W1, W2, Wh);

    // Phase 1: edge scatter — one warp per edge
    {
        int grid = EE / 8;   // 8 warps (edges) per 256-thread block
        scatter_kernel<<<grid, 256>>>((const float4*)n_feats, src, dst, e_feats);
    }

    // Phase 2: fused GEMM + bias epilogue
    {
        int grid = (NN + 63) / 64;   // 782
        gemm_kernel<<<grid, 256>>>(n_feats, b0, b1, b2, bh, out);
    }
}